// round 3
// baseline (speedup 1.0000x reference)
#include <cuda_runtime.h>
#include <math.h>
#include <stdint.h>

#define BATCH 16
#define H 1024
#define W 1024
#define HW (H * W)
#define NQ 4
#define CAP 131072
#define EPSV 1e-6f

// ---------------- device scratch ----------------
__device__ unsigned g_hist1[BATCH][8192];
__device__ unsigned g_cnt[BATCH][4];
__device__ unsigned g_cand[BATCH][4][CAP];
__device__ unsigned g_slotbin[BATCH][4];
__device__ float    g_slot_lo[BATCH][4];
__device__ float    g_slot_hi[BATCH][4];
__device__ int      g_tslot[BATCH][NQ];
__device__ int      g_trank[BATCH][NQ];
__device__ int      g_nslots[BATCH];
__device__ float    g_qval[BATCH][NQ];

__constant__ int c_dy[8] = {0, -1, -1, -1, 0, 1, 1, 1};
__constant__ int c_dx[8] = {1, 1, 0, -1, -1, -1, 0, 1};

__device__ __forceinline__ unsigned f2key(float f) {
    unsigned u = __float_as_uint(f);
    return (u & 0x80000000u) ? ~u : (u | 0x80000000u);
}
__device__ __forceinline__ float key2f(unsigned k) {
    unsigned u = (k & 0x80000000u) ? (k & 0x7fffffffu) : ~k;
    return __uint_as_float(u);
}

// ---------------- init: zero histograms ----------------
__global__ void k_init() {
    int i = blockIdx.x * blockDim.x + threadIdx.x;
    int stride = gridDim.x * blockDim.x;
    unsigned* h = &g_hist1[0][0];
    for (int j = i; j < BATCH * 8192; j += stride) h[j] = 0u;
}

// ---------------- pass 1: 13-bit-digit histogram ----------------
__global__ void k_hist(const float* __restrict__ x) {
    __shared__ unsigned sh[8192];
    int b = blockIdx.y;
    for (int i = threadIdx.x; i < 8192; i += blockDim.x) sh[i] = 0u;
    __syncthreads();
    const float4* xb = (const float4*)(x + (size_t)b * HW);
    const int nvec = HW / 4;
    for (int i = blockIdx.x * blockDim.x + threadIdx.x; i < nvec; i += gridDim.x * blockDim.x) {
        float4 v = xb[i];
        atomicAdd(&sh[f2key(v.x) >> 19], 1u);
        atomicAdd(&sh[f2key(v.y) >> 19], 1u);
        atomicAdd(&sh[f2key(v.z) >> 19], 1u);
        atomicAdd(&sh[f2key(v.w) >> 19], 1u);
    }
    __syncthreads();
    for (int i = threadIdx.x; i < 8192; i += blockDim.x) {
        unsigned c = sh[i];
        if (c) atomicAdd(&g_hist1[b][i], c);
    }
}

// ---------------- warp-parallel histogram walk ----------------
__device__ __forceinline__ int warp_walk(const unsigned* hist, int nb, int& rank) {
    int lane = threadIdx.x & 31;
    int chunk = nb / 32;
    const unsigned* hc = hist + lane * chunk;
    unsigned s = 0;
    for (int j = 0; j < chunk; j++) s += hc[j];
    unsigned inc = s;
    for (int o = 1; o < 32; o <<= 1) {
        unsigned v = __shfl_up_sync(0xffffffffu, inc, o);
        if (lane >= o) inc += v;
    }
    unsigned ex = inc - s;
    unsigned ball = __ballot_sync(0xffffffffu, (int)ex <= rank);
    int sel = 31 - __clz(ball);
    int d = 0, r = rank;
    if (lane == sel) {
        r = rank - (int)ex;
        d = lane * chunk;
        for (int j = 0; j < chunk; j++) {
            unsigned c = hc[j];
            if (r < (int)c) { d = lane * chunk + j; break; }
            r -= (int)c;
        }
    }
    d = __shfl_sync(0xffffffffu, d, sel);
    r = __shfl_sync(0xffffffffu, r, sel);
    rank = r;
    return d;
}

// ---------------- locate bins, dedupe into slots ----------------
__global__ void k_scan1() {
    int b = blockIdx.x;
    __shared__ int sm_bin[4], sm_rank[4];
    const int ranks[4] = {20971, 20972, 1027603, 1027604};
    int w = threadIdx.x >> 5;
    if (w < 4) {
        int r = ranks[w];
        int d = warp_walk(g_hist1[b], 8192, r);
        if ((threadIdx.x & 31) == 0) { sm_bin[w] = d; sm_rank[w] = r; }
    }
    __syncthreads();
    if (threadIdx.x == 0) {
        int ns = 0;
        for (int t = 0; t < NQ; t++) {
            int s = -1;
            for (int u = 0; u < ns; u++)
                if (g_slotbin[b][u] == (unsigned)sm_bin[t]) s = u;
            if (s < 0) {
                s = ns++;
                g_slotbin[b][s] = (unsigned)sm_bin[t];
                unsigned lo = (unsigned)sm_bin[t] << 19;
                g_slot_lo[b][s] = key2f(lo);
                g_slot_hi[b][s] = (sm_bin[t] == 8191) ? __int_as_float(0x7f800000)
                                                      : key2f(lo + (1u << 19));
                g_cnt[b][s] = 0u;
            }
            g_tslot[b][t] = s;
            g_trank[b][t] = sm_rank[t];
        }
        g_nslots[b] = ns;
        for (int s = ns; s < 4; s++) {
            g_slot_lo[b][s] = __int_as_float(0x7f800000);
            g_slot_hi[b][s] = __int_as_float(0x7f800000);
        }
    }
}

// ---------------- pass 2: collect candidates in target slots ----------------
__global__ void k_collect(const float* __restrict__ x) {
    __shared__ float slo[4], shi[4];
    int b = blockIdx.y;
    if (threadIdx.x < 4) {
        slo[threadIdx.x] = g_slot_lo[b][threadIdx.x];
        shi[threadIdx.x] = g_slot_hi[b][threadIdx.x];
    }
    __syncthreads();
    float l0 = slo[0], h0 = shi[0], l1 = slo[1], h1 = shi[1];
    float l2 = slo[2], h2 = shi[2], l3 = slo[3], h3 = shi[3];
    int lane = threadIdx.x & 31;

    const float4* xb = (const float4*)(x + (size_t)b * HW);
    const int nvec = HW / 4;
    for (int i = blockIdx.x * blockDim.x + threadIdx.x; i < nvec; i += gridDim.x * blockDim.x) {
        float4 v4 = xb[i];
        float vs[4] = {v4.x, v4.y, v4.z, v4.w};
#pragma unroll
        for (int e = 0; e < 4; e++) {
            float v = vs[e];
            int s = -1;
            if (v >= l0 && v < h0) s = 0;
            else if (v >= l1 && v < h1) s = 1;
            else if (v >= l2 && v < h2) s = 2;
            else if (v >= l3 && v < h3) s = 3;
            unsigned grp = __match_any_sync(0xffffffffu, s);
            if (s >= 0) {
                int leader = __ffs(grp) - 1;
                unsigned base = 0;
                if (lane == leader) base = atomicAdd(&g_cnt[b][s], (unsigned)__popc(grp));
                base = __shfl_sync(grp, base, leader);
                unsigned idx = base + (unsigned)__popc(grp & ((1u << lane) - 1u));
                if (idx < CAP) g_cand[b][s][idx] = f2key(v);
            }
        }
    }
}

// ---------------- exact select over 19 residual bits ----------------
__global__ void k_select() {
    int b = blockIdx.x >> 2, s = blockIdx.x & 3;
    __shared__ unsigned h1[2048];
    __shared__ unsigned h2[4][256];
    __shared__ int s_nt, s_tid[4], s_rank[4], s_d1[4];
    __shared__ unsigned s_base;
    if (threadIdx.x == 0) {
        int nt = 0;
        if (s < g_nslots[b]) {
            for (int t = 0; t < NQ; t++)
                if (g_tslot[b][t] == s) { s_tid[nt] = t; s_rank[nt] = g_trank[b][t]; nt++; }
            s_base = g_slotbin[b][s] << 19;
        }
        s_nt = nt;
    }
    __syncthreads();
    int nt = s_nt;
    if (nt == 0) return;
    unsigned n = g_cnt[b][s];
    if (n > CAP) n = CAP;
    const unsigned* cand = g_cand[b][s];

    for (int i = threadIdx.x; i < 2048; i += blockDim.x) h1[i] = 0u;
    __syncthreads();
    for (unsigned i = threadIdx.x; i < n; i += blockDim.x)
        atomicAdd(&h1[(cand[i] >> 8) & 2047u], 1u);
    __syncthreads();
    int w = threadIdx.x >> 5;
    if (w < nt) {
        int r = s_rank[w];
        int d = warp_walk(h1, 2048, r);
        if ((threadIdx.x & 31) == 0) { s_d1[w] = d; s_rank[w] = r; }
    }
    __syncthreads();
    for (int i = threadIdx.x; i < 4 * 256; i += blockDim.x) ((unsigned*)h2)[i] = 0u;
    __syncthreads();
    for (unsigned i = threadIdx.x; i < n; i += blockDim.x) {
        unsigned k = cand[i];
        unsigned hi = (k >> 8) & 2047u;
        for (int tt = 0; tt < nt; tt++)
            if (hi == (unsigned)s_d1[tt]) atomicAdd(&h2[tt][k & 255u], 1u);
    }
    __syncthreads();
    if (w < nt) {
        int r = s_rank[w];
        int d0 = warp_walk(&h2[w][0], 256, r);
        if ((threadIdx.x & 31) == 0) {
            unsigned key = s_base | ((unsigned)s_d1[w] << 8) | (unsigned)d0;
            g_qval[b][s_tid[w]] = key2f(key);
        }
    }
}

// ---------------- fused: normalize + sobel + octant + dir-max + end map ----------------
#define TS 32
#define HALO 6
#define SW (TS + 2 * HALO)   // 44
#define SPITCH (SW + 1)      // 45

__global__ __launch_bounds__(256) void k_fused(const float* __restrict__ x,
                                               float* __restrict__ emap,
                                               float* __restrict__ binsf,
                                               float* __restrict__ xnout) {
    __shared__ float tile[SW * SPITCH];
    int b = blockIdx.z;
    int bx = blockIdx.x * TS, by = blockIdx.y * TS;
    const float* xb = x + (size_t)b * HW;

    float q0 = g_qval[b][0], q1 = g_qval[b][1];
    float q2 = g_qval[b][2], q3 = g_qval[b][3];
    float lo = q0 + 0.5f * (q1 - q0);
    float hi = q2 + 0.5f * (q3 - q2);
    float den = hi - lo + EPSV;

    for (int i = threadIdx.x; i < SW * SW; i += blockDim.x) {
        int r = i / SW, c = i % SW;
        int gy = by + r - HALO, gx = bx + c - HALO;
        float v = 0.f;
        if ((unsigned)gy < H && (unsigned)gx < W)
            v = fminf(fmaxf((xb[gy * W + gx] - lo) / den, 0.f), 1.f);
        tile[r * SPITCH + c] = v;
    }
    __syncthreads();

    int lx = threadIdx.x & 31;
    int ly0 = threadIdx.x >> 5;
#pragma unroll
    for (int k = 0; k < 4; k++) {
        int ly = ly0 + k * 8;
        int ty = ly + HALO, tx = lx + HALO;
        const float* t0 = &tile[ty * SPITCH + tx];

        float a00 = t0[-SPITCH - 1], a01 = t0[-SPITCH], a02 = t0[-SPITCH + 1];
        float a10 = t0[-1], a12 = t0[1];
        float a20 = t0[SPITCH - 1], a21 = t0[SPITCH], a22 = t0[SPITCH + 1];
        float gxs = (a02 - a00) + 2.f * (a12 - a10) + (a22 - a20);
        float gys = (a20 - a00) + 2.f * (a21 - a01) + (a22 - a02);

        // exact octant of atan2(gys, gxs) mod 2pi, bins of pi/4,
        // boundary ties resolved upward (matching floor(atan2/step))
        int bin;
        if (gxs > 0.f && gys >= 0.f)      bin = (gys < gxs) ? 0 : 1;
        else if (gys > 0.f)               bin = (-gxs < gys) ? 2 : 3;
        else if (gxs < 0.f)               bin = (-gys < -gxs) ? 4 : 5;
        else if (gys < 0.f)               bin = (gxs < -gys) ? 6 : 7;
        else                              bin = 0;
        int b8 = (bin + 2) & 7;

        int dy = c_dy[b8], dx = c_dx[b8];
        int step = dy * SPITCH + dx;
        float f = 0.f, w = 0.f;
#pragma unroll
        for (int r = 1; r <= 6; r++) {
            f = fmaxf(f, t0[-step * r]);
            w = fmaxf(w, t0[ step * r]);
        }
        float mn = fminf(f, w), mx = fmaxf(f, w);
        float ratio = mn / (mx + EPSV);
        float x0 = t0[0];
        float em = fminf(fmaxf(x0 * (1.f - ratio), 0.f), 1.f);

        size_t o = (size_t)b * HW + (size_t)(by + ly) * W + (bx + lx);
        emap[o] = em;
        if (binsf) binsf[o] = (float)b8;
        if (xnout) xnout[o] = x0;
    }
}

// ---------------- launch ----------------
extern "C" void kernel_launch(void* const* d_in, const int* in_sizes, int n_in,
                              void* d_out, int out_size) {
    const float* x = (const float*)d_in[0];
    float* out = (float*)d_out;
    const size_t N = (size_t)BATCH * HW;

    float* emap  = out;
    float* binsf = ((size_t)out_size >= 2 * N) ? out + N : nullptr;
    float* xnout = ((size_t)out_size >= 3 * N) ? out + 2 * N : nullptr;

    k_init<<<128, 256>>>();
    dim3 g(32, BATCH);
    k_hist<<<g, 256>>>(x);
    k_scan1<<<BATCH, 128>>>();
    k_collect<<<dim3(64, BATCH), 256>>>(x);
    k_select<<<BATCH * 4, 256>>>();

    dim3 gf(W / TS, H / TS, BATCH);
    k_fused<<<gf, 256>>>(x, emap, binsf, xnout);
}

// round 4
// speedup vs baseline: 1.4076x; 1.4076x over previous
#include <cuda_runtime.h>
#include <math.h>
#include <stdint.h>

#define BATCH 16
#define H 1024
#define W 1024
#define HW (H * W)
#define CAP 262144
#define BUF 4096
#define TWO_PI_F 6.28318530717958647692f
#define STEP_F 0.78539816339744830962f
#define EPSV 1e-6f

// ---------------- device scratch ----------------
__device__ unsigned g_hist[BATCH][8192];
__device__ unsigned g_cnt[BATCH][2];
__device__ unsigned g_cand[BATCH][2][CAP];
__device__ float    g_rlo[BATCH][2];
__device__ float    g_rhi[BATCH][2];
__device__ int      g_snt[BATCH][2];        // targets per slot
__device__ int      g_stid[BATCH][2][4];    // target ids per slot
__device__ int      g_srank[BATCH][2][4];   // in-slot ranks per target
__device__ float    g_qval[BATCH][4];

__constant__ int c_dy[8] = {0, -1, -1, -1, 0, 1, 1, 1};
__constant__ int c_dx[8] = {1, 1, 0, -1, -1, -1, 0, 1};

__device__ __forceinline__ unsigned f2key(float f) {
    unsigned u = __float_as_uint(f);
    return (u & 0x80000000u) ? ~u : (u | 0x80000000u);
}
__device__ __forceinline__ float key2f(unsigned k) {
    unsigned u = (k & 0x80000000u) ? (k & 0x7fffffffu) : ~k;
    return __uint_as_float(u);
}

// ---------------- init ----------------
__global__ void k_init() {
    int i = blockIdx.x * blockDim.x + threadIdx.x;
    int stride = gridDim.x * blockDim.x;
    unsigned* h = &g_hist[0][0];
    for (int j = i; j < BATCH * 8192; j += stride) h[j] = 0u;
}

// ---------------- pass 1: 13-bit histogram, plain smem atomics ----------------
__global__ void k_hist(const float* __restrict__ x) {
    __shared__ unsigned sh[8192];
    int b = blockIdx.y;
    for (int i = threadIdx.x; i < 8192; i += blockDim.x) sh[i] = 0u;
    __syncthreads();
    const float4* xb = (const float4*)(x + (size_t)b * HW);
    const int nvec = HW / 4;
    for (int i = blockIdx.x * blockDim.x + threadIdx.x; i < nvec; i += gridDim.x * blockDim.x) {
        float4 v = xb[i];
        atomicAdd(&sh[f2key(v.x) >> 19], 1u);
        atomicAdd(&sh[f2key(v.y) >> 19], 1u);
        atomicAdd(&sh[f2key(v.z) >> 19], 1u);
        atomicAdd(&sh[f2key(v.w) >> 19], 1u);
    }
    __syncthreads();
    for (int i = threadIdx.x; i < 8192; i += blockDim.x) {
        unsigned c = sh[i];
        if (c) atomicAdd(&g_hist[b][i], c);
    }
}

// ---------------- warp-parallel histogram walk (full-mask shuffles only) ----------------
__device__ __forceinline__ int warp_walk(const unsigned* hist, int nb, int& rank) {
    int lane = threadIdx.x & 31;
    int chunk = nb / 32;
    const unsigned* hc = hist + lane * chunk;
    unsigned s = 0;
    for (int j = 0; j < chunk; j++) s += hc[j];
    unsigned inc = s;
#pragma unroll
    for (int o = 1; o < 32; o <<= 1) {
        unsigned v = __shfl_up_sync(0xffffffffu, inc, o);
        if (lane >= o) inc += v;
    }
    unsigned ex = inc - s;
    unsigned ball = __ballot_sync(0xffffffffu, (int)ex <= rank);
    int sel = 31 - __clz(ball);
    int d = 0, r = rank;
    if (lane == sel) {
        r = rank - (int)ex;
        d = lane * chunk;
        for (int j = 0; j < chunk; j++) {
            unsigned c = hc[j];
            if (r < (int)c) { d = lane * chunk + j; break; }
            r -= (int)c;
        }
    }
    d = __shfl_sync(0xffffffffu, d, sel);
    r = __shfl_sync(0xffffffffu, r, sel);
    rank = r;
    return d;
}

// ---------------- locate bins, build contiguous-range slots ----------------
__global__ void k_scan1() {
    int b = blockIdx.x;
    __shared__ int sbin[4], srank[4];
    const int ranks[4] = {20971, 20972, 1027603, 1027604};
    int w = threadIdx.x >> 5;
    if (w < 4) {
        int r = ranks[w];
        int d = warp_walk(g_hist[b], 8192, r);
        if ((threadIdx.x & 31) == 0) { sbin[w] = d; srank[w] = r; }
    }
    __syncthreads();
    if (threadIdx.x == 0) {
        float inf = __int_as_float(0x7f800000);
        int c0 = ranks[0] - srank[0];   // cumcount below sbin[0]
        int c2 = ranks[2] - srank[2];   // cumcount below sbin[2]
        bool merged = (sbin[2] <= sbin[1]);
        int b0lo = sbin[0];
        int b0hi = merged ? sbin[3] : sbin[1];
        g_rlo[b][0] = key2f((unsigned)b0lo << 19);
        g_rhi[b][0] = (b0hi == 8191) ? inf : key2f(((unsigned)b0hi + 1u) << 19);
        g_cnt[b][0] = 0u;
        g_cnt[b][1] = 0u;
        if (merged) {
            g_snt[b][0] = 4; g_snt[b][1] = 0;
            g_rlo[b][1] = inf; g_rhi[b][1] = inf;
            for (int t = 0; t < 4; t++) { g_stid[b][0][t] = t; g_srank[b][0][t] = ranks[t] - c0; }
        } else {
            g_snt[b][0] = 2; g_snt[b][1] = 2;
            g_rlo[b][1] = key2f((unsigned)sbin[2] << 19);
            g_rhi[b][1] = (sbin[3] == 8191) ? inf : key2f(((unsigned)sbin[3] + 1u) << 19);
            for (int t = 0; t < 2; t++) { g_stid[b][0][t] = t;     g_srank[b][0][t] = ranks[t] - c0; }
            for (int t = 0; t < 2; t++) { g_stid[b][1][t] = 2 + t; g_srank[b][1][t] = ranks[2 + t] - c2; }
        }
    }
}

// ---------------- pass 2: collect candidates (smem-staged, no warp voting) ----------------
__global__ __launch_bounds__(256) void k_collect(const float* __restrict__ x) {
    __shared__ unsigned scnt[2];
    __shared__ unsigned sbase[2];
    __shared__ unsigned sbuf[2][BUF];
    int b = blockIdx.y;
    if (threadIdx.x < 2) scnt[threadIdx.x] = 0u;
    __syncthreads();
    float l0 = g_rlo[b][0], h0 = g_rhi[b][0];
    float l1 = g_rlo[b][1], h1 = g_rhi[b][1];

    const float4* xb = (const float4*)(x + (size_t)b * HW);
    const int nvec = HW / 4;
    for (int i = blockIdx.x * blockDim.x + threadIdx.x; i < nvec; i += gridDim.x * blockDim.x) {
        float4 v4 = xb[i];
        float vs[4] = {v4.x, v4.y, v4.z, v4.w};
#pragma unroll
        for (int e = 0; e < 4; e++) {
            float v = vs[e];
            int s = -1;
            if (v >= l0 && v < h0) s = 0;
            else if (v >= l1 && v < h1) s = 1;
            if (s >= 0) {
                unsigned p = atomicAdd(&scnt[s], 1u);
                if (p < BUF) sbuf[s][p] = f2key(v);
                else {
                    unsigned gi = atomicAdd(&g_cnt[b][s], 1u);
                    if (gi < CAP) g_cand[b][s][gi] = f2key(v);
                }
            }
        }
    }
    __syncthreads();
    if (threadIdx.x < 2) {
        unsigned m = min(scnt[threadIdx.x], (unsigned)BUF);
        sbase[threadIdx.x] = atomicAdd(&g_cnt[b][threadIdx.x], m);
    }
    __syncthreads();
#pragma unroll
    for (int s = 0; s < 2; s++) {
        unsigned m = min(scnt[s], (unsigned)BUF);
        unsigned base = sbase[s];
        for (unsigned j = threadIdx.x; j < m; j += blockDim.x)
            if (base + j < CAP) g_cand[b][s][base + j] = sbuf[s][j];
    }
}

// ---------------- exact 3-level select over full 32-bit candidate keys ----------------
__global__ void k_select() {
    int b = blockIdx.x >> 1, s = blockIdx.x & 1;
    __shared__ unsigned h1[2048];
    __shared__ unsigned hT[4][2048];
    __shared__ int s_d1[4], s_d2[4], s_rank[4];
    int nt = g_snt[b][s];
    if (nt == 0) return;
    unsigned n = g_cnt[b][s];
    if (n > CAP) n = CAP;
    const unsigned* cand = g_cand[b][s];
    int w = threadIdx.x >> 5;

    if (threadIdx.x < 4) s_rank[threadIdx.x] = g_srank[b][s][threadIdx.x];
    for (int i = threadIdx.x; i < 2048; i += blockDim.x) h1[i] = 0u;
    __syncthreads();
    // level 1: bits 31..21
    for (unsigned i = threadIdx.x; i < n; i += blockDim.x)
        atomicAdd(&h1[cand[i] >> 21], 1u);
    __syncthreads();
    if (w < nt) {
        int r = s_rank[w];
        int d = warp_walk(h1, 2048, r);
        if ((threadIdx.x & 31) == 0) { s_d1[w] = d; s_rank[w] = r; }
    }
    __syncthreads();
    // level 2: bits 20..10, per target
    for (int i = threadIdx.x; i < 4 * 2048; i += blockDim.x) ((unsigned*)hT)[i] = 0u;
    __syncthreads();
    for (unsigned i = threadIdx.x; i < n; i += blockDim.x) {
        unsigned k = cand[i];
        unsigned p = k >> 21;
        unsigned dig = (k >> 10) & 2047u;
        for (int tt = 0; tt < nt; tt++)
            if (p == (unsigned)s_d1[tt]) atomicAdd(&hT[tt][dig], 1u);
    }
    __syncthreads();
    if (w < nt) {
        int r = s_rank[w];
        int d = warp_walk(&hT[w][0], 2048, r);
        if ((threadIdx.x & 31) == 0) { s_d2[w] = d; s_rank[w] = r; }
    }
    __syncthreads();
    // level 3: bits 9..0, per target
    for (int i = threadIdx.x; i < 4 * 2048; i += blockDim.x) ((unsigned*)hT)[i] = 0u;
    __syncthreads();
    for (unsigned i = threadIdx.x; i < n; i += blockDim.x) {
        unsigned k = cand[i];
        unsigned p = k >> 10;
        for (int tt = 0; tt < nt; tt++)
            if (p == (((unsigned)s_d1[tt] << 11) | (unsigned)s_d2[tt]))
                atomicAdd(&hT[tt][k & 1023u], 1u);
    }
    __syncthreads();
    if (w < nt) {
        int r = s_rank[w];
        int d = warp_walk(&hT[w][0], 1024, r);
        if ((threadIdx.x & 31) == 0) {
            unsigned key = ((unsigned)s_d1[w] << 21) | ((unsigned)s_d2[w] << 10) | (unsigned)d;
            g_qval[b][g_stid[b][s][w]] = key2f(key);
        }
    }
}

// ---------------- fused: normalize + sobel + atan2 + dir-max + end map ----------------
#define TS 32
#define HALO 6
#define SW (TS + 2 * HALO)   // 44
#define SPITCH (SW + 1)      // 45

__global__ __launch_bounds__(256) void k_fused(const float* __restrict__ x,
                                               float* __restrict__ emap,
                                               float* __restrict__ binsf,
                                               float* __restrict__ xnout) {
    __shared__ float tile[SW * SPITCH];
    int b = blockIdx.z;
    int bx = blockIdx.x * TS, by = blockIdx.y * TS;
    const float* xb = x + (size_t)b * HW;

    float q0 = g_qval[b][0], q1 = g_qval[b][1];
    float q2 = g_qval[b][2], q3 = g_qval[b][3];
    float lo = q0 + 0.5f * (q1 - q0);
    float hi = q2 + 0.5f * (q3 - q2);
    float den = hi - lo + EPSV;

    for (int i = threadIdx.x; i < SW * SW; i += blockDim.x) {
        int r = i / SW, c = i % SW;
        int gy = by + r - HALO, gx = bx + c - HALO;
        float v = 0.f;
        if ((unsigned)gy < H && (unsigned)gx < W)
            v = fminf(fmaxf((xb[gy * W + gx] - lo) / den, 0.f), 1.f);
        tile[r * SPITCH + c] = v;
    }
    __syncthreads();

    int lx = threadIdx.x & 31;
    int ly0 = threadIdx.x >> 5;
#pragma unroll
    for (int k = 0; k < 4; k++) {
        int ly = ly0 + k * 8;
        int ty = ly + HALO, tx = lx + HALO;
        const float* t0 = &tile[ty * SPITCH + tx];

        float a00 = t0[-SPITCH - 1], a01 = t0[-SPITCH], a02 = t0[-SPITCH + 1];
        float a10 = t0[-1], a12 = t0[1];
        float a20 = t0[SPITCH - 1], a21 = t0[SPITCH], a22 = t0[SPITCH + 1];
        float gxs = (a02 - a00) + 2.f * (a12 - a10) + (a22 - a20);
        float gys = (a20 - a00) + 2.f * (a21 - a01) + (a22 - a02);

        float ang = atan2f(gys, gxs);
        if (ang < 0.f) ang += TWO_PI_F;
        int bin = (int)floorf(ang / STEP_F);
        bin = min(max(bin, 0), 7);
        int b8 = (bin + 2) & 7;

        int dy = c_dy[b8], dx = c_dx[b8];
        int step = dy * SPITCH + dx;
        float f = 0.f, w = 0.f;
#pragma unroll
        for (int r = 1; r <= 6; r++) {
            f = fmaxf(f, t0[-step * r]);
            w = fmaxf(w, t0[ step * r]);
        }
        float mn = fminf(f, w), mx = fmaxf(f, w);
        float ratio = mn / (mx + EPSV);
        float x0 = t0[0];
        float em = fminf(fmaxf(x0 * (1.f - ratio), 0.f), 1.f);

        size_t o = (size_t)b * HW + (size_t)(by + ly) * W + (bx + lx);
        emap[o] = em;
        if (binsf) binsf[o] = (float)b8;
        if (xnout) xnout[o] = x0;
    }
}

// ---------------- launch ----------------
extern "C" void kernel_launch(void* const* d_in, const int* in_sizes, int n_in,
                              void* d_out, int out_size) {
    const float* x = (const float*)d_in[0];
    float* out = (float*)d_out;
    const size_t N = (size_t)BATCH * HW;

    float* emap  = out;
    float* binsf = ((size_t)out_size >= 2 * N) ? out + N : nullptr;
    float* xnout = ((size_t)out_size >= 3 * N) ? out + 2 * N : nullptr;

    k_init<<<64, 256>>>();
    k_hist<<<dim3(32, BATCH), 256>>>(x);
    k_scan1<<<BATCH, 128>>>();
    k_collect<<<dim3(64, BATCH), 256>>>(x);
    k_select<<<BATCH * 2, 256>>>();

    dim3 gf(W / TS, H / TS, BATCH);
    k_fused<<<gf, 256>>>(x, emap, binsf, xnout);
}